// round 15
// baseline (speedup 1.0000x reference)
#include <cuda_runtime.h>
#include <cuda_bf16.h>
#include <cstdint>

// Problem constants
constexpr int B = 128, T = 16, L = 196, E = 512, H = 1024, V = 32000;

// ---------------- scratch (device globals; no allocations allowed) ----------
__device__ __nv_bfloat16 g_keys[(size_t)B * L * H];        // 51.4 MB
__device__ __nv_bfloat16 g_featsbf[(size_t)B * L * E];     // 25.7 MB
__device__ __nv_bfloat16 g_woutbf[(size_t)H * V];          // 65.5 MB [K,N]
__device__ __nv_bfloat16 g_wgbf2[(size_t)1536 * 4096];     // 12.6 MB [K,N]: [W_lstm_z; U_lstm]
__device__ __nv_bfloat16 g_wlxbf[(size_t)512 * 4096];      // 4.2 MB  [K,N]: W_lstm_x
__device__ __nv_bfloat16 g_wqbbf[(size_t)1024 * 1536];     // 3.1 MB  [K,N]
__device__ __nv_bfloat16 g_wihbf[(size_t)E * H];
__device__ __nv_bfloat16 g_wicbf[(size_t)E * H];
__device__ __nv_bfloat16 g_uabf[(size_t)E * H];
__device__ __nv_bfloat16 g_hbf[T + 1][B * H];              // h ring: one slot per step (no reuse -> no race)
__device__ __nv_bfloat16 g_ctx2[B * 1536];                 // [zβ | h]
__device__ __nv_bfloat16 g_meanbf[B * E];
__device__ __nv_bfloat16 g_capemb[(size_t)B * T * E];
__device__ float g_c[B * H];
__device__ float g_qbp[4 * B * 1536];
__device__ float g_e[B * L];
__device__ float g_gatesx[(size_t)B * T * 4096];           // 33.6 MB (x_t @ W_lstm_x + b)
__device__ float g_gatesp[4 * B * 4096];
__device__ float g_logits[(size_t)B * V];                  // 16.4 MB

// ---------------- helpers ---------------------------------------------------
__device__ __forceinline__ float warpReduceSum(float v) {
    #pragma unroll
    for (int o = 16; o > 0; o >>= 1) v += __shfl_xor_sync(0xFFFFFFFFu, v, o);
    return v;
}
__device__ __forceinline__ float warpReduceMax(float v) {
    #pragma unroll
    for (int o = 16; o > 0; o >>= 1) v = fmaxf(v, __shfl_xor_sync(0xFFFFFFFFu, v, o));
    return v;
}
__device__ __forceinline__ float sigmoidf(float x) { return 1.0f / (1.0f + __expf(-x)); }

__device__ __forceinline__ void ldsm_x4(uint32_t* r, uint32_t addr) {
    asm volatile("ldmatrix.sync.aligned.m8n8.x4.shared.b16 {%0,%1,%2,%3}, [%4];"
                 : "=r"(r[0]), "=r"(r[1]), "=r"(r[2]), "=r"(r[3]) : "r"(addr));
}
__device__ __forceinline__ void ldsm_x4_t(uint32_t* r, uint32_t addr) {
    asm volatile("ldmatrix.sync.aligned.m8n8.x4.trans.shared.b16 {%0,%1,%2,%3}, [%4];"
                 : "=r"(r[0]), "=r"(r[1]), "=r"(r[2]), "=r"(r[3]) : "r"(addr));
}
__device__ __forceinline__ void mma_bf16(float* c, const uint32_t* a, uint32_t b0, uint32_t b1) {
    asm volatile(
        "mma.sync.aligned.m16n8k16.row.col.f32.bf16.bf16.f32 "
        "{%0,%1,%2,%3},{%4,%5,%6,%7},{%8,%9},{%0,%1,%2,%3};"
        : "+f"(c[0]), "+f"(c[1]), "+f"(c[2]), "+f"(c[3])
        : "r"(a[0]), "r"(a[1]), "r"(a[2]), "r"(a[3]), "r"(b0), "r"(b1));
}
__device__ __forceinline__ void cp16(uint32_t dst, const void* src) {
    asm volatile("cp.async.cg.shared.global [%0], [%1], 16;" :: "r"(dst), "l"(src) : "memory");
}
#define CP_COMMIT() asm volatile("cp.async.commit_group;" ::: "memory")
#define CP_WAIT(n)  asm volatile("cp.async.wait_group %0;" :: "n"(n) : "memory")

// ---------------- HMMA GEMM (proven): BM=128 BN=128 BK=32, 3-stage ----------
constexpr int ASTG = 128 * 80;           // A stage bytes (LDA=40 bf16)
constexpr int BSTG = 32 * 272;           // B stage bytes (LDB=136 bf16)
constexpr int STG  = ASTG + BSTG;        // 18944
constexpr int GSMEM = 3 * STG;           // 56832

template <int SPLITK, bool OUT_BF, bool BIAS>
__global__ __launch_bounds__(256) void gemm_hmma(
    const __nv_bfloat16* __restrict__ A, const __nv_bfloat16* __restrict__ Bw,
    const float* __restrict__ bias, void* __restrict__ Cv, int M, int N, int K)
{
    extern __shared__ char sm[];
    const int tid  = threadIdx.x;
    const int lane = tid & 31;
    const int warp = tid >> 5;
    const int wm = (warp & 1) * 64;
    const int wn = (warp >> 1) * 32;
    const int m0 = blockIdx.y * 128;
    const int n0 = blockIdx.x * 128;
    const int Kc = K / SPLITK;
    const int kbase = (SPLITK > 1) ? blockIdx.z * Kc : 0;
    const int KT = Kc / 32;

    const uint32_t smb = (uint32_t)__cvta_generic_to_shared(sm);

    auto issue = [&](int kt, int s) {
        const int k0 = kbase + kt * 32;
        const uint32_t base = smb + s * STG;
        {
            int i = tid;
            int row = i >> 2, cc = i & 3;
            cp16(base + row * 80 + cc * 16, A + (size_t)(m0 + row) * K + k0 + cc * 8);
            i = tid + 256;
            row = i >> 2; cc = i & 3;
            cp16(base + row * 80 + cc * 16, A + (size_t)(m0 + row) * K + k0 + cc * 8);
        }
        {
            int i = tid;
            int row = i >> 4, cc = i & 15;
            cp16(base + ASTG + row * 272 + cc * 16, Bw + (size_t)(k0 + row) * N + n0 + cc * 8);
            i = tid + 256;
            row = i >> 4; cc = i & 15;
            cp16(base + ASTG + row * 272 + cc * 16, Bw + (size_t)(k0 + row) * N + n0 + cc * 8);
        }
    };

    float acc[4][4][4] = {};

    issue(0, 0); CP_COMMIT();
    if (KT > 1) { issue(1, 1); CP_COMMIT(); }

    for (int kt = 0; kt < KT; kt++) {
        CP_WAIT(1);
        __syncthreads();
        if (kt + 2 < KT) issue(kt + 2, (kt + 2) % 3);
        CP_COMMIT();

        const uint32_t ab = smb + (kt % 3) * STG;
        const uint32_t bb = ab + ASTG;
        #pragma unroll
        for (int ks = 0; ks < 2; ks++) {
            uint32_t a[4][4], b0[4], b1[4];
            #pragma unroll
            for (int mt = 0; mt < 4; mt++)
                ldsm_x4(a[mt], ab + (wm + mt * 16 + (lane & 15)) * 80
                                  + ks * 32 + ((lane >> 4) & 1) * 16);
            const uint32_t brow = bb + (ks * 16 + (lane & 15)) * 272
                                     + (wn + ((lane >> 4) & 1) * 8) * 2;
            ldsm_x4_t(b0, brow);
            ldsm_x4_t(b1, brow + 32);
            #pragma unroll
            for (int mt = 0; mt < 4; mt++) {
                mma_bf16(acc[mt][0], a[mt], b0[0], b0[1]);
                mma_bf16(acc[mt][1], a[mt], b0[2], b0[3]);
                mma_bf16(acc[mt][2], a[mt], b1[0], b1[1]);
                mma_bf16(acc[mt][3], a[mt], b1[2], b1[3]);
            }
        }
        __syncthreads();
    }

    const int r0 = m0 + wm + (lane >> 2);
    const int c0 = n0 + wn + (lane & 3) * 2;
    #pragma unroll
    for (int mt = 0; mt < 4; mt++) {
        #pragma unroll
        for (int nt = 0; nt < 4; nt++) {
            const int r = r0 + mt * 16;
            const int cix = c0 + nt * 8;
            float b0v = BIAS ? bias[cix] : 0.f;
            float b1v = BIAS ? bias[cix + 1] : 0.f;
            float v0 = acc[mt][nt][0] + b0v, v1 = acc[mt][nt][1] + b1v;
            float v2 = acc[mt][nt][2] + b0v, v3 = acc[mt][nt][3] + b1v;
            if (OUT_BF) {
                __nv_bfloat16* C = (__nv_bfloat16*)Cv;
                *(__nv_bfloat162*)(C + (size_t)r * N + cix)       = __floats2bfloat162_rn(v0, v1);
                *(__nv_bfloat162*)(C + (size_t)(r + 8) * N + cix) = __floats2bfloat162_rn(v2, v3);
            } else {
                float* C = (float*)Cv + (SPLITK > 1 ? (size_t)blockIdx.z * M * N : 0);
                *(float2*)(C + (size_t)r * N + cix)       = make_float2(v0, v1);
                *(float2*)(C + (size_t)(r + 8) * N + cix) = make_float2(v2, v3);
            }
        }
    }
}

// ---------------- wide HMMA GEMM for logits: BM=128 BN=256, 4-stage ---------
constexpr int B2STG = 32 * 528;          // B stage bytes (LDB=264 bf16)
constexpr int STG2  = ASTG + B2STG;      // 27136
constexpr int GSMEM2 = 4 * STG2;         // 108544

__global__ __launch_bounds__(256, 1) void gemm_hmma_n256(
    const __nv_bfloat16* __restrict__ A, const __nv_bfloat16* __restrict__ Bw,
    const float* __restrict__ bias, float* __restrict__ C, int M, int N, int K)
{
    extern __shared__ char sm[];
    const int tid  = threadIdx.x;
    const int lane = tid & 31;
    const int warp = tid >> 5;
    const int wm = (warp & 1) * 64;
    const int wn = (warp >> 1) * 64;
    const int m0 = blockIdx.y * 128;
    const int n0 = blockIdx.x * 256;
    const int KT = K / 32;

    const uint32_t smb = (uint32_t)__cvta_generic_to_shared(sm);

    auto issue = [&](int kt, int s) {
        const int k0 = kt * 32;
        const uint32_t base = smb + s * STG2;
        #pragma unroll
        for (int p = 0; p < 2; p++) {
            int i = tid + p * 256;
            int row = i >> 2, cc = i & 3;
            cp16(base + row * 80 + cc * 16, A + (size_t)(m0 + row) * K + k0 + cc * 8);
        }
        #pragma unroll
        for (int p = 0; p < 4; p++) {
            int i = tid + p * 256;
            int row = i >> 5, cc = i & 31;
            cp16(base + ASTG + row * 528 + cc * 16, Bw + (size_t)(k0 + row) * N + n0 + cc * 8);
        }
    };

    float acc[4][8][4] = {};

    // prologue: exactly 3 committed groups (deeper lookahead vs 3-stage)
    #pragma unroll
    for (int s = 0; s < 3; s++) {
        if (s < KT) issue(s, s);
        CP_COMMIT();
    }

    for (int kt = 0; kt < KT; kt++) {
        CP_WAIT(2);
        __syncthreads();
        if (kt + 3 < KT) issue(kt + 3, (kt + 3) & 3);
        CP_COMMIT();

        const uint32_t ab = smb + (kt & 3) * STG2;
        const uint32_t bb = ab + ASTG;
        #pragma unroll
        for (int ks = 0; ks < 2; ks++) {
            uint32_t a[4][4], bfr[4][4];
            #pragma unroll
            for (int mt = 0; mt < 4; mt++)
                ldsm_x4(a[mt], ab + (wm + mt * 16 + (lane & 15)) * 80
                                  + ks * 32 + ((lane >> 4) & 1) * 16);
            #pragma unroll
            for (int p = 0; p < 4; p++)
                ldsm_x4_t(bfr[p], bb + (ks * 16 + (lane & 15)) * 528
                                     + (wn + p * 16 + ((lane >> 4) & 1) * 8) * 2);
            #pragma unroll
            for (int mt = 0; mt < 4; mt++) {
                #pragma unroll
                for (int p = 0; p < 4; p++) {
                    mma_bf16(acc[mt][2 * p],     a[mt], bfr[p][0], bfr[p][1]);
                    mma_bf16(acc[mt][2 * p + 1], a[mt], bfr[p][2], bfr[p][3]);
                }
            }
        }
        __syncthreads();
    }

    const int r0 = m0 + wm + (lane >> 2);
    const int c0 = n0 + wn + (lane & 3) * 2;
    #pragma unroll
    for (int mt = 0; mt < 4; mt++) {
        #pragma unroll
        for (int nt = 0; nt < 8; nt++) {
            const int r = r0 + mt * 16;
            const int cix = c0 + nt * 8;
            float b0v = bias[cix], b1v = bias[cix + 1];
            *(float2*)(C + (size_t)r * N + cix) =
                make_float2(acc[mt][nt][0] + b0v, acc[mt][nt][1] + b1v);
            *(float2*)(C + (size_t)(r + 8) * N + cix) =
                make_float2(acc[mt][nt][2] + b0v, acc[mt][nt][3] + b1v);
        }
    }
}

// ---------------- prologue kernels -------------------------------------------
__global__ void f2bf_copy(const float* __restrict__ src, __nv_bfloat16* __restrict__ dst, size_t n4) {
    size_t i = (size_t)blockIdx.x * blockDim.x + threadIdx.x;
    size_t stride = (size_t)gridDim.x * blockDim.x;
    for (; i < n4; i += stride) {
        float4 v = ((const float4*)src)[i];
        __nv_bfloat162* d = (__nv_bfloat162*)(dst + i * 4);
        d[0] = __floats2bfloat162_rn(v.x, v.y);
        d[1] = __floats2bfloat162_rn(v.z, v.w);
    }
}

__global__ void f2bf_cat(const float* __restrict__ src, int Rows, int Cols,
                         __nv_bfloat16* __restrict__ dst, int dstLd, int rowOff, int colOff) {
    int idx = blockIdx.x * blockDim.x + threadIdx.x;
    if (idx * 4 >= Rows * Cols) return;
    int r = (idx * 4) / Cols, c = (idx * 4) % Cols;
    float4 v = *(const float4*)(src + (size_t)r * Cols + c);
    __nv_bfloat162* d = (__nv_bfloat162*)(dst + (size_t)(r + rowOff) * dstLd + colOff + c);
    d[0] = __floats2bfloat162_rn(v.x, v.y);
    d[1] = __floats2bfloat162_rn(v.z, v.w);
}

// row-slice copy: dst[dstRow0 + r][c] = bf16(src[srcRow0 + r][c]), r in [0, nRows)
__global__ void f2bf_rows(const float* __restrict__ src, int srcRow0, int Cols, int nRows,
                          __nv_bfloat16* __restrict__ dst, int dstLd, int dstRow0) {
    int idx = blockIdx.x * blockDim.x + threadIdx.x;
    if (idx * 4 >= nRows * Cols) return;
    int r = (idx * 4) / Cols, c = (idx * 4) % Cols;
    float4 v = *(const float4*)(src + (size_t)(srcRow0 + r) * Cols + c);
    __nv_bfloat162* d = (__nv_bfloat162*)(dst + (size_t)(dstRow0 + r) * dstLd + c);
    d[0] = __floats2bfloat162_rn(v.x, v.y);
    d[1] = __floats2bfloat162_rn(v.z, v.w);
}

__global__ void gather_emb(const int* __restrict__ cap, const float* __restrict__ emb,
                           __nv_bfloat16* __restrict__ capemb) {
    int idx = blockIdx.x * blockDim.x + threadIdx.x;   // B*T*E
    int e = idx % E, bt = idx / E;
    capemb[idx] = __float2bfloat16(emb[(size_t)cap[bt] * E + e]);
}

__global__ void row_mean(const float* __restrict__ feats, __nv_bfloat16* __restrict__ mean) {
    int b = blockIdx.x, e = threadIdx.x;               // blockDim = 512
    float s = 0.f;
    const float* base = feats + (size_t)b * L * E + e;
    for (int l = 0; l < L; l++) s += base[(size_t)l * E];
    mean[b * E + e] = __float2bfloat16(s * (1.0f / (float)L));
}

__global__ void copy_h0(const __nv_bfloat16* __restrict__ hbf, __nv_bfloat16* __restrict__ ctx2) {
    int idx = blockIdx.x * blockDim.x + threadIdx.x;   // B*H
    int b = idx / H, j = idx % H;
    ctx2[(size_t)b * 1536 + 512 + j] = hbf[idx];
}

// ---------------- per-step small kernels -------------------------------------
// attn_e: warp-per-l, no in-loop barriers. Grid (7, B), 128 threads (4 warps).
__global__ __launch_bounds__(128) void attn_e(
    const __nv_bfloat16* __restrict__ keys, const float* __restrict__ qbp,
    const float* __restrict__ ba, const float* __restrict__ Va,
    const float* __restrict__ bva, float* __restrict__ e)
{
    const int b = blockIdx.y;
    const int tid = threadIdx.x;
    const int lane = tid & 31, warp = tid >> 5;
    __shared__ float qs[H];
    __shared__ float vs[H];
    const size_t qoff = (size_t)b * 1536;
    for (int i = tid; i < H; i += 128) {
        float s = ba[i];
        #pragma unroll
        for (int z = 0; z < 4; z++) s += qbp[(size_t)z * B * 1536 + qoff + i];
        qs[i] = s;
        vs[i] = Va[i];
    }
    __syncthreads();

    const float bva0 = bva[0];
    const int l0 = blockIdx.x * 28 + warp * 7;         // warp's 7 l values
    #pragma unroll 1
    for (int li = 0; li < 7; li++) {
        const int l = l0 + li;
        const __nv_bfloat16* kr = keys + ((size_t)b * L + l) * H;
        uint4 kv[4];
        #pragma unroll
        for (int r = 0; r < 4; r++)
            kv[r] = *(const uint4*)(kr + r * 256 + lane * 8);
        float s = 0.f;
        #pragma unroll
        for (int r = 0; r < 4; r++) {
            const __nv_bfloat162* kp = (const __nv_bfloat162*)&kv[r];
            const int i0 = r * 256 + lane * 8;
            #pragma unroll
            for (int j = 0; j < 4; j++) {
                float2 kf = __bfloat1622float2(kp[j]);
                int i = i0 + j * 2;
                s = fmaf(fmaxf(qs[i] + kf.x, 0.f), vs[i], s);
                s = fmaf(fmaxf(qs[i + 1] + kf.y, 0.f), vs[i + 1], s);
            }
        }
        s = warpReduceSum(s);
        if (lane == 0) e[b * L + l] = s + bva0;
    }
}

// fused: softmax over L + z-sum + beta gate; writes ctx2[b][0:512] = bf(z*sig(beta))
__global__ __launch_bounds__(512) void z_ctx(
    const float* __restrict__ eb, const __nv_bfloat16* __restrict__ featsbf,
    const float* __restrict__ qbp, const float* __restrict__ bbeta,
    __nv_bfloat16* __restrict__ ctx2)
{
    const int b = blockIdx.x, tid = threadIdx.x;
    const int lane = tid & 31, warp = tid >> 5;       // 16 warps
    const int grp = tid >> 7, col = tid & 127;        // 4 groups x 128 quad-cols
    __shared__ float al[L];
    __shared__ float4 part[4][128];
    __shared__ float red[16];

    // softmax over L
    {
        float v = (tid < L) ? eb[b * L + tid] : -1e30f;
        float m = warpReduceMax(v);
        if (lane == 0) red[warp] = m;
        __syncthreads();
        if (tid < 32) { float x = (tid < 16) ? red[tid] : -1e30f; x = warpReduceMax(x); if (tid == 0) red[0] = x; }
        __syncthreads();
        const float mm = red[0];
        float ex = (tid < L) ? __expf(v - mm) : 0.f;
        float s = warpReduceSum(ex);
        __syncthreads();
        if (lane == 0) red[warp] = s;
        __syncthreads();
        if (tid < 32) { float x = (tid < 16) ? red[tid] : 0.f; x = warpReduceSum(x); if (tid == 0) red[0] = x; }
        __syncthreads();
        if (tid < L) al[tid] = ex / red[0];
    }
    __syncthreads();

    const uint2* base = (const uint2*)(featsbf + (size_t)b * L * E) + col;
    float4 s = make_float4(0.f, 0.f, 0.f, 0.f);
    const int l0 = grp * 49;
    #pragma unroll 4
    for (int l = l0; l < l0 + 49; l++) {
        float a = al[l];
        uint2 u = base[(size_t)l * 128];
        float2 f01 = __bfloat1622float2(*(const __nv_bfloat162*)&u.x);
        float2 f23 = __bfloat1622float2(*(const __nv_bfloat162*)&u.y);
        s.x = fmaf(a, f01.x, s.x); s.y = fmaf(a, f01.y, s.y);
        s.z = fmaf(a, f23.x, s.z); s.w = fmaf(a, f23.y, s.w);
    }
    part[grp][col] = s;
    __syncthreads();
    if (grp == 0) {
        float4 a0 = part[0][col], a1 = part[1][col], a2 = part[2][col], a3 = part[3][col];
        float z4[4] = { a0.x + a1.x + a2.x + a3.x, a0.y + a1.y + a2.y + a3.y,
                        a0.z + a1.z + a2.z + a3.z, a0.w + a1.w + a2.w + a3.w };
        __nv_bfloat16* d = ctx2 + (size_t)b * 1536 + col * 4;
        const size_t qoff = (size_t)b * 1536 + 1024 + col * 4;
        #pragma unroll
        for (int u = 0; u < 4; u++) {
            float gb = bbeta[col * 4 + u];
            #pragma unroll
            for (int z = 0; z < 4; z++) gb += qbp[(size_t)z * B * 1536 + qoff + u];
            d[u] = __float2bfloat16(z4[u] * sigmoidf(gb));
        }
    }
}

__global__ void lstm_elem(const float* __restrict__ gp, const float* __restrict__ gx,
                          float* __restrict__ c, __nv_bfloat16* __restrict__ hout,
                          __nv_bfloat16* __restrict__ ctx2, int t) {
    int idx = blockIdx.x * blockDim.x + threadIdx.x;  // B*H
    int b = idx / H, j = idx % H;
    const size_t base = (size_t)b * 4096;
    const float* gxr = gx + ((size_t)b * T + t) * 4096;
    float gi = gxr[j], gf = gxr[H + j], gg = gxr[2 * H + j], go = gxr[3 * H + j];
    #pragma unroll
    for (int z = 0; z < 4; z++) {
        const float* g = gp + (size_t)z * B * 4096 + base;
        gi += g[j]; gf += g[H + j]; gg += g[2 * H + j]; go += g[3 * H + j];
    }
    float i_ = sigmoidf(gi), f_ = sigmoidf(gf), g_ = tanhf(gg), o_ = sigmoidf(go);
    float cn = f_ * c[idx] + i_ * g_;
    c[idx] = cn;
    __nv_bfloat16 hn = __float2bfloat16(o_ * tanhf(cn));
    hout[idx] = hn;
    ctx2[(size_t)b * 1536 + 512 + j] = hn;
}

__global__ __launch_bounds__(1024) void softmax_V(const float* __restrict__ logits,
                                                  float* __restrict__ out, int t) {
    extern __shared__ float xs[];                      // 32000 floats
    const int b = blockIdx.x, tid = threadIdx.x;
    const float* x = logits + (size_t)b * V;
    float* y = out + ((size_t)b * T + t) * V;
    __shared__ float red[32];

    float m = -1e30f;
    for (int i = tid; i < V; i += 1024) { float v = x[i]; xs[i] = v; m = fmaxf(m, v); }
    m = warpReduceMax(m);
    if ((tid & 31) == 0) red[tid >> 5] = m;
    __syncthreads();
    if (tid < 32) { float v = red[tid]; v = warpReduceMax(v); red[tid] = v; }
    __syncthreads();
    const float mm = red[0];

    float s = 0.f;
    for (int i = tid; i < V; i += 1024) s += __expf(xs[i] - mm);
    s = warpReduceSum(s);
    __syncthreads();
    if ((tid & 31) == 0) red[tid >> 5] = s;
    __syncthreads();
    if (tid < 32) { float v = red[tid]; v = warpReduceSum(v); red[tid] = v; }
    __syncthreads();
    const float inv = 1.0f / red[0];
    for (int i = tid; i < V; i += 1024) y[i] = __expf(xs[i] - mm) * inv;
}

// ---------------- launch ------------------------------------------------------
extern "C" void kernel_launch(void* const* d_in, const int* in_sizes, int n_in,
                              void* d_out, int out_size) {
    const int*   cap      = (const int*)  d_in[0];
    const float* feats    = (const float*)d_in[1];
    const float* emb      = (const float*)d_in[2];
    const float* W_init_h = (const float*)d_in[3];
    const float* b_init_h = (const float*)d_in[4];
    const float* W_init_c = (const float*)d_in[5];
    const float* b_init_c = (const float*)d_in[6];
    const float* W_a      = (const float*)d_in[7];
    const float* b_a      = (const float*)d_in[8];
    const float* U_a      = (const float*)d_in[9];
    const float* b_ua     = (const float*)d_in[10];
    const float* V_a      = (const float*)d_in[11];
    const float* b_va     = (const float*)d_in[12];
    const float* W_beta   = (const float*)d_in[13];
    const float* b_beta   = (const float*)d_in[14];
    const float* W_lstm   = (const float*)d_in[15];
    const float* U_lstm   = (const float*)d_in[16];
    const float* b_lstm   = (const float*)d_in[17];
    const float* W_out    = (const float*)d_in[18];
    const float* b_out    = (const float*)d_in[19];
    float* out = (float*)d_out;

    __nv_bfloat16 *keys, *featsbf, *woutbf, *wgbf2, *wlxbf, *wqbbf, *wihbf, *wicbf, *uabf,
                  *hbuf, *ctx2, *meanbf, *capemb;
    float *cst, *qbp, *eb, *gatesx, *gatesp, *logits;
    cudaGetSymbolAddress((void**)&keys,    g_keys);
    cudaGetSymbolAddress((void**)&featsbf, g_featsbf);
    cudaGetSymbolAddress((void**)&woutbf,  g_woutbf);
    cudaGetSymbolAddress((void**)&wgbf2,   g_wgbf2);
    cudaGetSymbolAddress((void**)&wlxbf,   g_wlxbf);
    cudaGetSymbolAddress((void**)&wqbbf,   g_wqbbf);
    cudaGetSymbolAddress((void**)&wihbf,   g_wihbf);
    cudaGetSymbolAddress((void**)&wicbf,   g_wicbf);
    cudaGetSymbolAddress((void**)&uabf,    g_uabf);
    cudaGetSymbolAddress((void**)&hbuf,    g_hbf);
    cudaGetSymbolAddress((void**)&ctx2,    g_ctx2);
    cudaGetSymbolAddress((void**)&meanbf,  g_meanbf);
    cudaGetSymbolAddress((void**)&capemb,  g_capemb);
    cudaGetSymbolAddress((void**)&cst,     g_c);
    cudaGetSymbolAddress((void**)&qbp,     g_qbp);
    cudaGetSymbolAddress((void**)&eb,      g_e);
    cudaGetSymbolAddress((void**)&gatesx,  g_gatesx);
    cudaGetSymbolAddress((void**)&gatesp,  g_gatesp);
    cudaGetSymbolAddress((void**)&logits,  g_logits);

    // h ring buffer: slot t holds h(t); never overwritten within a replay.
    auto hslot = [&](int t) { return hbuf + (size_t)t * B * H; };

    cudaFuncSetAttribute(gemm_hmma<1, true,  true>,  cudaFuncAttributeMaxDynamicSharedMemorySize, GSMEM);
    cudaFuncSetAttribute(gemm_hmma<1, false, true>,  cudaFuncAttributeMaxDynamicSharedMemorySize, GSMEM);
    cudaFuncSetAttribute(gemm_hmma<4, false, false>, cudaFuncAttributeMaxDynamicSharedMemorySize, GSMEM);
    cudaFuncSetAttribute(gemm_hmma_n256, cudaFuncAttributeMaxDynamicSharedMemorySize, GSMEM2);
    cudaFuncSetAttribute(softmax_V, cudaFuncAttributeMaxDynamicSharedMemorySize, V * 4);

    // secondary stream + events
    cudaStream_t sA;
    cudaStreamCreateWithFlags(&sA, cudaStreamNonBlocking);
    cudaEvent_t evH[T], evO, evG, evX;
    for (int t = 0; t < T; t++) cudaEventCreateWithFlags(&evH[t], cudaEventDisableTiming);
    cudaEventCreateWithFlags(&evO, cudaEventDisableTiming);
    cudaEventCreateWithFlags(&evG, cudaEventDisableTiming);
    cudaEventCreateWithFlags(&evX, cudaEventDisableTiming);

    // ---- prologue (dual-stream) ----
    // stream 0: everything step-0's attention chain needs (keys GEMM is the long pole)
    f2bf_copy<<<2048, 256>>>(feats, featsbf, (size_t)B * L * E / 4);
    gather_emb<<<(B * T * E) / 256, 256>>>(cap, emb, capemb);
    cudaEventRecord(evG, 0);                            // capemb ready (for gatesx on sA)
    row_mean<<<B, 512>>>(feats, meanbf);
    f2bf_copy<<<512, 256>>>(U_a, uabf, (size_t)E * H / 4);
    f2bf_cat<<<(1024 * 1024 / 4) / 256, 256>>>(W_a,    1024, 1024, wqbbf, 1536, 0, 0);
    f2bf_cat<<<(1024 * 512  / 4) / 256, 256>>>(W_beta, 1024, 512,  wqbbf, 1536, 0, 1024);
    f2bf_rows<<<(512  * 4096 / 4) / 256, 256>>>(W_lstm, 0, 4096, 512,  wgbf2, 4096, 0);
    f2bf_rows<<<(1024 * 4096 / 4) / 256, 256>>>(U_lstm, 0, 4096, 1024, wgbf2, 4096, 512);
    f2bf_copy<<<512, 256>>>(W_init_h, wihbf, (size_t)E * H / 4);
    f2bf_copy<<<512, 256>>>(W_init_c, wicbf, (size_t)E * H / 4);
    gemm_hmma<1, true,  true><<<dim3(8, 1), 256, GSMEM>>>(meanbf, wihbf, b_init_h, hslot(0), 128, H, E);
    gemm_hmma<1, false, true><<<dim3(8, 1), 256, GSMEM>>>(meanbf, wicbf, b_init_c, cst, 128, H, E);
    copy_h0<<<(B * H) / 256, 256>>>(hslot(0), ctx2);
    gemm_hmma<1, true, true><<<dim3(8, B * L / 128), 256, GSMEM>>>(featsbf, uabf, b_ua, keys, B * L, H, E);

    // stream A: output-branch weights + gatesx precompute (overlaps keys GEMM)
    f2bf_rows<<<(512 * 4096 / 4) / 256, 256, 0, sA>>>(W_lstm, 512, 4096, 512, wlxbf, 4096, 0);
    f2bf_copy<<<2048, 256, 0, sA>>>(W_out, woutbf, (size_t)H * V / 4);
    cudaStreamWaitEvent(sA, evG, 0);
    gemm_hmma<1, false, true><<<dim3(4096 / 128, (B * T) / 128), 256, GSMEM, sA>>>(
        capemb, wlxbf, b_lstm, gatesx, B * T, 4096, 512);
    cudaEventRecord(evX, sA);
    cudaStreamWaitEvent(0, evX, 0);    // gatesx ready before first lstm_elem (free: keys GEMM outlasts sA)

    // ---- time steps ----
    for (int t = 0; t < T; t++) {
        const __nv_bfloat16* h_in  = hslot(t);          // h(t)
        __nv_bfloat16*       h_out = hslot(t + 1);      // h(t+1) — fresh slot, no reuse

        // attention / LSTM chain (stream 0 = critical path)
        gemm_hmma<4, false, false><<<dim3(12, 1, 4), 256, GSMEM>>>(h_in, wqbbf, nullptr, qbp, 128, 1536, 1024);
        attn_e<<<dim3(7, B), 128>>>(keys, qbp, b_a, V_a, b_va, eb);
        z_ctx<<<B, 512>>>(eb, featsbf, qbp, b_beta, ctx2);
        gemm_hmma<4, false, false><<<dim3(32, 1, 4), 256, GSMEM>>>(ctx2, wgbf2, nullptr, gatesp, 128, 4096, 1536);
        lstm_elem<<<(B * H) / 256, 256>>>(gatesp, gatesx, cst, h_out, ctx2, t);

        // fork: output branch on stream A (full 125-CTA grid, 4-stage pipeline)
        cudaEventRecord(evH[t], 0);
        cudaStreamWaitEvent(sA, evH[t], 0);
        gemm_hmma_n256<<<dim3(V / 256, 1), 256, GSMEM2, sA>>>(h_out, woutbf, b_out, logits, 128, V, H);
        softmax_V<<<B, 1024, V * 4, sA>>>(logits, out, t);
    }

    // join output branch back into the main stream
    cudaEventRecord(evO, sA);
    cudaStreamWaitEvent(0, evO, 0);
}

// round 16
// speedup vs baseline: 1.0502x; 1.0502x over previous
#include <cuda_runtime.h>
#include <cuda_bf16.h>
#include <cstdint>

// Problem constants
constexpr int B = 128, T = 16, L = 196, E = 512, H = 1024, V = 32000;

// ---------------- scratch (device globals; no allocations allowed) ----------
__device__ __nv_bfloat16 g_keys[(size_t)B * L * H];        // 51.4 MB
__device__ __nv_bfloat16 g_featsbf[(size_t)B * L * E];     // 25.7 MB
__device__ __nv_bfloat16 g_woutbf[(size_t)H * V];          // 65.5 MB [K,N]
__device__ __nv_bfloat16 g_wgbf2[(size_t)1536 * 4096];     // 12.6 MB [K,N]: [W_lstm_z; U_lstm]
__device__ __nv_bfloat16 g_wlxbf[(size_t)512 * 4096];      // 4.2 MB  [K,N]: W_lstm_x
__device__ __nv_bfloat16 g_wqbbf[(size_t)1024 * 1536];     // 3.1 MB  [K,N]
__device__ __nv_bfloat16 g_wihbf[(size_t)E * H];
__device__ __nv_bfloat16 g_wicbf[(size_t)E * H];
__device__ __nv_bfloat16 g_uabf[(size_t)E * H];
__device__ __nv_bfloat16 g_hbf[T + 1][B * H];              // h ring: one slot per step (no reuse -> no race)
__device__ __nv_bfloat16 g_ctx2[B * 1536];                 // [zβ | h]
__device__ __nv_bfloat16 g_meanbf[B * E];
__device__ __nv_bfloat16 g_capemb[(size_t)B * T * E];
__device__ float g_c[B * H];
__device__ float g_qbp[4 * B * 1536];
__device__ float g_e[B * L];
__device__ float g_gatesx[(size_t)B * T * 4096];           // 33.6 MB (x_t @ W_lstm_x + b)
__device__ float g_gatesp[4 * B * 4096];
__device__ float g_logits[(size_t)B * V];                  // 16.4 MB

// ---------------- helpers ---------------------------------------------------
__device__ __forceinline__ float warpReduceSum(float v) {
    #pragma unroll
    for (int o = 16; o > 0; o >>= 1) v += __shfl_xor_sync(0xFFFFFFFFu, v, o);
    return v;
}
__device__ __forceinline__ float warpReduceMax(float v) {
    #pragma unroll
    for (int o = 16; o > 0; o >>= 1) v = fmaxf(v, __shfl_xor_sync(0xFFFFFFFFu, v, o));
    return v;
}
__device__ __forceinline__ float sigmoidf(float x) { return 1.0f / (1.0f + __expf(-x)); }

__device__ __forceinline__ void ldsm_x4(uint32_t* r, uint32_t addr) {
    asm volatile("ldmatrix.sync.aligned.m8n8.x4.shared.b16 {%0,%1,%2,%3}, [%4];"
                 : "=r"(r[0]), "=r"(r[1]), "=r"(r[2]), "=r"(r[3]) : "r"(addr));
}
__device__ __forceinline__ void ldsm_x4_t(uint32_t* r, uint32_t addr) {
    asm volatile("ldmatrix.sync.aligned.m8n8.x4.trans.shared.b16 {%0,%1,%2,%3}, [%4];"
                 : "=r"(r[0]), "=r"(r[1]), "=r"(r[2]), "=r"(r[3]) : "r"(addr));
}
__device__ __forceinline__ void mma_bf16(float* c, const uint32_t* a, uint32_t b0, uint32_t b1) {
    asm volatile(
        "mma.sync.aligned.m16n8k16.row.col.f32.bf16.bf16.f32 "
        "{%0,%1,%2,%3},{%4,%5,%6,%7},{%8,%9},{%0,%1,%2,%3};"
        : "+f"(c[0]), "+f"(c[1]), "+f"(c[2]), "+f"(c[3])
        : "r"(a[0]), "r"(a[1]), "r"(a[2]), "r"(a[3]), "r"(b0), "r"(b1));
}
__device__ __forceinline__ void cp16(uint32_t dst, const void* src) {
    asm volatile("cp.async.cg.shared.global [%0], [%1], 16;" :: "r"(dst), "l"(src) : "memory");
}
#define CP_COMMIT() asm volatile("cp.async.commit_group;" ::: "memory")
#define CP_WAIT(n)  asm volatile("cp.async.wait_group %0;" :: "n"(n) : "memory")

// ---------------- HMMA GEMM: BM=128 BN=128 BK=32, 3-stage, 2 CTAs/SM --------
// __launch_bounds__(256, 2) caps regs at 128/thread so two GEMM CTAs (or a
// logits CTA + a chain CTA) co-reside per SM: 2*57KB smem, 2*~124*256 regs.
constexpr int ASTG = 128 * 80;           // A stage bytes (LDA=40 bf16)
constexpr int BSTG = 32 * 272;           // B stage bytes (LDB=136 bf16)
constexpr int STG  = ASTG + BSTG;        // 18944
constexpr int GSMEM = 3 * STG;           // 56832

template <int SPLITK, bool OUT_BF, bool BIAS>
__global__ __launch_bounds__(256, 2) void gemm_hmma(
    const __nv_bfloat16* __restrict__ A, const __nv_bfloat16* __restrict__ Bw,
    const float* __restrict__ bias, void* __restrict__ Cv, int M, int N, int K)
{
    extern __shared__ char sm[];
    const int tid  = threadIdx.x;
    const int lane = tid & 31;
    const int warp = tid >> 5;
    const int wm = (warp & 1) * 64;
    const int wn = (warp >> 1) * 32;
    const int m0 = blockIdx.y * 128;
    const int n0 = blockIdx.x * 128;
    const int Kc = K / SPLITK;
    const int kbase = (SPLITK > 1) ? blockIdx.z * Kc : 0;
    const int KT = Kc / 32;

    const uint32_t smb = (uint32_t)__cvta_generic_to_shared(sm);

    auto issue = [&](int kt, int s) {
        const int k0 = kbase + kt * 32;
        const uint32_t base = smb + s * STG;
        {
            int i = tid;
            int row = i >> 2, cc = i & 3;
            cp16(base + row * 80 + cc * 16, A + (size_t)(m0 + row) * K + k0 + cc * 8);
            i = tid + 256;
            row = i >> 2; cc = i & 3;
            cp16(base + row * 80 + cc * 16, A + (size_t)(m0 + row) * K + k0 + cc * 8);
        }
        {
            int i = tid;
            int row = i >> 4, cc = i & 15;
            cp16(base + ASTG + row * 272 + cc * 16, Bw + (size_t)(k0 + row) * N + n0 + cc * 8);
            i = tid + 256;
            row = i >> 4; cc = i & 15;
            cp16(base + ASTG + row * 272 + cc * 16, Bw + (size_t)(k0 + row) * N + n0 + cc * 8);
        }
    };

    float acc[4][4][4] = {};

    issue(0, 0); CP_COMMIT();
    if (KT > 1) { issue(1, 1); CP_COMMIT(); }

    for (int kt = 0; kt < KT; kt++) {
        CP_WAIT(1);
        __syncthreads();
        if (kt + 2 < KT) issue(kt + 2, (kt + 2) % 3);
        CP_COMMIT();

        const uint32_t ab = smb + (kt % 3) * STG;
        const uint32_t bb = ab + ASTG;
        #pragma unroll
        for (int ks = 0; ks < 2; ks++) {
            uint32_t a[4][4], b0[4], b1[4];
            #pragma unroll
            for (int mt = 0; mt < 4; mt++)
                ldsm_x4(a[mt], ab + (wm + mt * 16 + (lane & 15)) * 80
                                  + ks * 32 + ((lane >> 4) & 1) * 16);
            const uint32_t brow = bb + (ks * 16 + (lane & 15)) * 272
                                     + (wn + ((lane >> 4) & 1) * 8) * 2;
            ldsm_x4_t(b0, brow);
            ldsm_x4_t(b1, brow + 32);
            #pragma unroll
            for (int mt = 0; mt < 4; mt++) {
                mma_bf16(acc[mt][0], a[mt], b0[0], b0[1]);
                mma_bf16(acc[mt][1], a[mt], b0[2], b0[3]);
                mma_bf16(acc[mt][2], a[mt], b1[0], b1[1]);
                mma_bf16(acc[mt][3], a[mt], b1[2], b1[3]);
            }
        }
        __syncthreads();
    }

    const int r0 = m0 + wm + (lane >> 2);
    const int c0 = n0 + wn + (lane & 3) * 2;
    #pragma unroll
    for (int mt = 0; mt < 4; mt++) {
        #pragma unroll
        for (int nt = 0; nt < 4; nt++) {
            const int r = r0 + mt * 16;
            const int cix = c0 + nt * 8;
            float b0v = BIAS ? bias[cix] : 0.f;
            float b1v = BIAS ? bias[cix + 1] : 0.f;
            float v0 = acc[mt][nt][0] + b0v, v1 = acc[mt][nt][1] + b1v;
            float v2 = acc[mt][nt][2] + b0v, v3 = acc[mt][nt][3] + b1v;
            if (OUT_BF) {
                __nv_bfloat16* C = (__nv_bfloat16*)Cv;
                *(__nv_bfloat162*)(C + (size_t)r * N + cix)       = __floats2bfloat162_rn(v0, v1);
                *(__nv_bfloat162*)(C + (size_t)(r + 8) * N + cix) = __floats2bfloat162_rn(v2, v3);
            } else {
                float* C = (float*)Cv + (SPLITK > 1 ? (size_t)blockIdx.z * M * N : 0);
                *(float2*)(C + (size_t)r * N + cix)       = make_float2(v0, v1);
                *(float2*)(C + (size_t)(r + 8) * N + cix) = make_float2(v2, v3);
            }
        }
    }
}

// ---------------- prologue kernels -------------------------------------------
__global__ void f2bf_copy(const float* __restrict__ src, __nv_bfloat16* __restrict__ dst, size_t n4) {
    size_t i = (size_t)blockIdx.x * blockDim.x + threadIdx.x;
    size_t stride = (size_t)gridDim.x * blockDim.x;
    for (; i < n4; i += stride) {
        float4 v = ((const float4*)src)[i];
        __nv_bfloat162* d = (__nv_bfloat162*)(dst + i * 4);
        d[0] = __floats2bfloat162_rn(v.x, v.y);
        d[1] = __floats2bfloat162_rn(v.z, v.w);
    }
}

__global__ void f2bf_cat(const float* __restrict__ src, int Rows, int Cols,
                         __nv_bfloat16* __restrict__ dst, int dstLd, int rowOff, int colOff) {
    int idx = blockIdx.x * blockDim.x + threadIdx.x;
    if (idx * 4 >= Rows * Cols) return;
    int r = (idx * 4) / Cols, c = (idx * 4) % Cols;
    float4 v = *(const float4*)(src + (size_t)r * Cols + c);
    __nv_bfloat162* d = (__nv_bfloat162*)(dst + (size_t)(r + rowOff) * dstLd + colOff + c);
    d[0] = __floats2bfloat162_rn(v.x, v.y);
    d[1] = __floats2bfloat162_rn(v.z, v.w);
}

// row-slice copy: dst[dstRow0 + r][c] = bf16(src[srcRow0 + r][c]), r in [0, nRows)
__global__ void f2bf_rows(const float* __restrict__ src, int srcRow0, int Cols, int nRows,
                          __nv_bfloat16* __restrict__ dst, int dstLd, int dstRow0) {
    int idx = blockIdx.x * blockDim.x + threadIdx.x;
    if (idx * 4 >= nRows * Cols) return;
    int r = (idx * 4) / Cols, c = (idx * 4) % Cols;
    float4 v = *(const float4*)(src + (size_t)(srcRow0 + r) * Cols + c);
    __nv_bfloat162* d = (__nv_bfloat162*)(dst + (size_t)(dstRow0 + r) * dstLd + c);
    d[0] = __floats2bfloat162_rn(v.x, v.y);
    d[1] = __floats2bfloat162_rn(v.z, v.w);
}

__global__ void gather_emb(const int* __restrict__ cap, const float* __restrict__ emb,
                           __nv_bfloat16* __restrict__ capemb) {
    int idx = blockIdx.x * blockDim.x + threadIdx.x;   // B*T*E
    int e = idx % E, bt = idx / E;
    capemb[idx] = __float2bfloat16(emb[(size_t)cap[bt] * E + e]);
}

__global__ void row_mean(const float* __restrict__ feats, __nv_bfloat16* __restrict__ mean) {
    int b = blockIdx.x, e = threadIdx.x;               // blockDim = 512
    float s = 0.f;
    const float* base = feats + (size_t)b * L * E + e;
    for (int l = 0; l < L; l++) s += base[(size_t)l * E];
    mean[b * E + e] = __float2bfloat16(s * (1.0f / (float)L));
}

__global__ void copy_h0(const __nv_bfloat16* __restrict__ hbf, __nv_bfloat16* __restrict__ ctx2) {
    int idx = blockIdx.x * blockDim.x + threadIdx.x;   // B*H
    int b = idx / H, j = idx % H;
    ctx2[(size_t)b * 1536 + 512 + j] = hbf[idx];
}

// ---------------- per-step small kernels -------------------------------------
// attn_e: warp-per-l, no in-loop barriers. Grid (7, B), 128 threads (4 warps).
__global__ __launch_bounds__(128) void attn_e(
    const __nv_bfloat16* __restrict__ keys, const float* __restrict__ qbp,
    const float* __restrict__ ba, const float* __restrict__ Va,
    const float* __restrict__ bva, float* __restrict__ e)
{
    const int b = blockIdx.y;
    const int tid = threadIdx.x;
    const int lane = tid & 31, warp = tid >> 5;
    __shared__ float qs[H];
    __shared__ float vs[H];
    const size_t qoff = (size_t)b * 1536;
    for (int i = tid; i < H; i += 128) {
        float s = ba[i];
        #pragma unroll
        for (int z = 0; z < 4; z++) s += qbp[(size_t)z * B * 1536 + qoff + i];
        qs[i] = s;
        vs[i] = Va[i];
    }
    __syncthreads();

    const float bva0 = bva[0];
    const int l0 = blockIdx.x * 28 + warp * 7;         // warp's 7 l values
    #pragma unroll 1
    for (int li = 0; li < 7; li++) {
        const int l = l0 + li;
        const __nv_bfloat16* kr = keys + ((size_t)b * L + l) * H;
        uint4 kv[4];
        #pragma unroll
        for (int r = 0; r < 4; r++)
            kv[r] = *(const uint4*)(kr + r * 256 + lane * 8);
        float s = 0.f;
        #pragma unroll
        for (int r = 0; r < 4; r++) {
            const __nv_bfloat162* kp = (const __nv_bfloat162*)&kv[r];
            const int i0 = r * 256 + lane * 8;
            #pragma unroll
            for (int j = 0; j < 4; j++) {
                float2 kf = __bfloat1622float2(kp[j]);
                int i = i0 + j * 2;
                s = fmaf(fmaxf(qs[i] + kf.x, 0.f), vs[i], s);
                s = fmaf(fmaxf(qs[i + 1] + kf.y, 0.f), vs[i + 1], s);
            }
        }
        s = warpReduceSum(s);
        if (lane == 0) e[b * L + l] = s + bva0;
    }
}

// fused: softmax over L + z-sum + beta gate; writes ctx2[b][0:512] = bf(z*sig(beta))
__global__ __launch_bounds__(512) void z_ctx(
    const float* __restrict__ eb, const __nv_bfloat16* __restrict__ featsbf,
    const float* __restrict__ qbp, const float* __restrict__ bbeta,
    __nv_bfloat16* __restrict__ ctx2)
{
    const int b = blockIdx.x, tid = threadIdx.x;
    const int lane = tid & 31, warp = tid >> 5;       // 16 warps
    const int grp = tid >> 7, col = tid & 127;        // 4 groups x 128 quad-cols
    __shared__ float al[L];
    __shared__ float4 part[4][128];
    __shared__ float red[16];

    // softmax over L
    {
        float v = (tid < L) ? eb[b * L + tid] : -1e30f;
        float m = warpReduceMax(v);
        if (lane == 0) red[warp] = m;
        __syncthreads();
        if (tid < 32) { float x = (tid < 16) ? red[tid] : -1e30f; x = warpReduceMax(x); if (tid == 0) red[0] = x; }
        __syncthreads();
        const float mm = red[0];
        float ex = (tid < L) ? __expf(v - mm) : 0.f;
        float s = warpReduceSum(ex);
        __syncthreads();
        if (lane == 0) red[warp] = s;
        __syncthreads();
        if (tid < 32) { float x = (tid < 16) ? red[tid] : 0.f; x = warpReduceSum(x); if (tid == 0) red[0] = x; }
        __syncthreads();
        if (tid < L) al[tid] = ex / red[0];
    }
    __syncthreads();

    const uint2* base = (const uint2*)(featsbf + (size_t)b * L * E) + col;
    float4 s = make_float4(0.f, 0.f, 0.f, 0.f);
    const int l0 = grp * 49;
    #pragma unroll 4
    for (int l = l0; l < l0 + 49; l++) {
        float a = al[l];
        uint2 u = base[(size_t)l * 128];
        float2 f01 = __bfloat1622float2(*(const __nv_bfloat162*)&u.x);
        float2 f23 = __bfloat1622float2(*(const __nv_bfloat162*)&u.y);
        s.x = fmaf(a, f01.x, s.x); s.y = fmaf(a, f01.y, s.y);
        s.z = fmaf(a, f23.x, s.z); s.w = fmaf(a, f23.y, s.w);
    }
    part[grp][col] = s;
    __syncthreads();
    if (grp == 0) {
        float4 a0 = part[0][col], a1 = part[1][col], a2 = part[2][col], a3 = part[3][col];
        float z4[4] = { a0.x + a1.x + a2.x + a3.x, a0.y + a1.y + a2.y + a3.y,
                        a0.z + a1.z + a2.z + a3.z, a0.w + a1.w + a2.w + a3.w };
        __nv_bfloat16* d = ctx2 + (size_t)b * 1536 + col * 4;
        const size_t qoff = (size_t)b * 1536 + 1024 + col * 4;
        #pragma unroll
        for (int u = 0; u < 4; u++) {
            float gb = bbeta[col * 4 + u];
            #pragma unroll
            for (int z = 0; z < 4; z++) gb += qbp[(size_t)z * B * 1536 + qoff + u];
            d[u] = __float2bfloat16(z4[u] * sigmoidf(gb));
        }
    }
}

__global__ void lstm_elem(const float* __restrict__ gp, const float* __restrict__ gx,
                          float* __restrict__ c, __nv_bfloat16* __restrict__ hout,
                          __nv_bfloat16* __restrict__ ctx2, int t) {
    int idx = blockIdx.x * blockDim.x + threadIdx.x;  // B*H
    int b = idx / H, j = idx % H;
    const size_t base = (size_t)b * 4096;
    const float* gxr = gx + ((size_t)b * T + t) * 4096;
    float gi = gxr[j], gf = gxr[H + j], gg = gxr[2 * H + j], go = gxr[3 * H + j];
    #pragma unroll
    for (int z = 0; z < 4; z++) {
        const float* g = gp + (size_t)z * B * 4096 + base;
        gi += g[j]; gf += g[H + j]; gg += g[2 * H + j]; go += g[3 * H + j];
    }
    float i_ = sigmoidf(gi), f_ = sigmoidf(gf), g_ = tanhf(gg), o_ = sigmoidf(go);
    float cn = f_ * c[idx] + i_ * g_;
    c[idx] = cn;
    __nv_bfloat16 hn = __float2bfloat16(o_ * tanhf(cn));
    hout[idx] = hn;
    ctx2[(size_t)b * 1536 + 512 + j] = hn;
}

__global__ __launch_bounds__(1024) void softmax_V(const float* __restrict__ logits,
                                                  float* __restrict__ out, int t) {
    extern __shared__ float xs[];                      // 32000 floats
    const int b = blockIdx.x, tid = threadIdx.x;
    const float* x = logits + (size_t)b * V;
    float* y = out + ((size_t)b * T + t) * V;
    __shared__ float red[32];

    float m = -1e30f;
    for (int i = tid; i < V; i += 1024) { float v = x[i]; xs[i] = v; m = fmaxf(m, v); }
    m = warpReduceMax(m);
    if ((tid & 31) == 0) red[tid >> 5] = m;
    __syncthreads();
    if (tid < 32) { float v = red[tid]; v = warpReduceMax(v); red[tid] = v; }
    __syncthreads();
    const float mm = red[0];

    float s = 0.f;
    for (int i = tid; i < V; i += 1024) s += __expf(xs[i] - mm);
    s = warpReduceSum(s);
    __syncthreads();
    if ((tid & 31) == 0) red[tid >> 5] = s;
    __syncthreads();
    if (tid < 32) { float v = red[tid]; v = warpReduceSum(v); red[tid] = v; }
    __syncthreads();
    const float inv = 1.0f / red[0];
    for (int i = tid; i < V; i += 1024) y[i] = __expf(xs[i] - mm) * inv;
}

// ---------------- launch ------------------------------------------------------
extern "C" void kernel_launch(void* const* d_in, const int* in_sizes, int n_in,
                              void* d_out, int out_size) {
    const int*   cap      = (const int*)  d_in[0];
    const float* feats    = (const float*)d_in[1];
    const float* emb      = (const float*)d_in[2];
    const float* W_init_h = (const float*)d_in[3];
    const float* b_init_h = (const float*)d_in[4];
    const float* W_init_c = (const float*)d_in[5];
    const float* b_init_c = (const float*)d_in[6];
    const float* W_a      = (const float*)d_in[7];
    const float* b_a      = (const float*)d_in[8];
    const float* U_a      = (const float*)d_in[9];
    const float* b_ua     = (const float*)d_in[10];
    const float* V_a      = (const float*)d_in[11];
    const float* b_va     = (const float*)d_in[12];
    const float* W_beta   = (const float*)d_in[13];
    const float* b_beta   = (const float*)d_in[14];
    const float* W_lstm   = (const float*)d_in[15];
    const float* U_lstm   = (const float*)d_in[16];
    const float* b_lstm   = (const float*)d_in[17];
    const float* W_out    = (const float*)d_in[18];
    const float* b_out    = (const float*)d_in[19];
    float* out = (float*)d_out;

    __nv_bfloat16 *keys, *featsbf, *woutbf, *wgbf2, *wlxbf, *wqbbf, *wihbf, *wicbf, *uabf,
                  *hbuf, *ctx2, *meanbf, *capemb;
    float *cst, *qbp, *eb, *gatesx, *gatesp, *logits;
    cudaGetSymbolAddress((void**)&keys,    g_keys);
    cudaGetSymbolAddress((void**)&featsbf, g_featsbf);
    cudaGetSymbolAddress((void**)&woutbf,  g_woutbf);
    cudaGetSymbolAddress((void**)&wgbf2,   g_wgbf2);
    cudaGetSymbolAddress((void**)&wlxbf,   g_wlxbf);
    cudaGetSymbolAddress((void**)&wqbbf,   g_wqbbf);
    cudaGetSymbolAddress((void**)&wihbf,   g_wihbf);
    cudaGetSymbolAddress((void**)&wicbf,   g_wicbf);
    cudaGetSymbolAddress((void**)&uabf,    g_uabf);
    cudaGetSymbolAddress((void**)&hbuf,    g_hbf);
    cudaGetSymbolAddress((void**)&ctx2,    g_ctx2);
    cudaGetSymbolAddress((void**)&meanbf,  g_meanbf);
    cudaGetSymbolAddress((void**)&capemb,  g_capemb);
    cudaGetSymbolAddress((void**)&cst,     g_c);
    cudaGetSymbolAddress((void**)&qbp,     g_qbp);
    cudaGetSymbolAddress((void**)&eb,      g_e);
    cudaGetSymbolAddress((void**)&gatesx,  g_gatesx);
    cudaGetSymbolAddress((void**)&gatesp,  g_gatesp);
    cudaGetSymbolAddress((void**)&logits,  g_logits);

    // h ring buffer: slot t holds h(t); never overwritten within a replay.
    auto hslot = [&](int t) { return hbuf + (size_t)t * B * H; };

    cudaFuncSetAttribute(gemm_hmma<1, true,  true>,  cudaFuncAttributeMaxDynamicSharedMemorySize, GSMEM);
    cudaFuncSetAttribute(gemm_hmma<1, false, true>,  cudaFuncAttributeMaxDynamicSharedMemorySize, GSMEM);
    cudaFuncSetAttribute(gemm_hmma<4, false, false>, cudaFuncAttributeMaxDynamicSharedMemorySize, GSMEM);
    cudaFuncSetAttribute(softmax_V, cudaFuncAttributeMaxDynamicSharedMemorySize, V * 4);

    // secondary stream + events
    cudaStream_t sA;
    cudaStreamCreateWithFlags(&sA, cudaStreamNonBlocking);
    cudaEvent_t evH[T], evO, evG, evX;
    for (int t = 0; t < T; t++) cudaEventCreateWithFlags(&evH[t], cudaEventDisableTiming);
    cudaEventCreateWithFlags(&evO, cudaEventDisableTiming);
    cudaEventCreateWithFlags(&evG, cudaEventDisableTiming);
    cudaEventCreateWithFlags(&evX, cudaEventDisableTiming);

    // ---- prologue (dual-stream) ----
    // stream 0: everything step-0's attention chain needs (keys GEMM is the long pole)
    f2bf_copy<<<2048, 256>>>(feats, featsbf, (size_t)B * L * E / 4);
    gather_emb<<<(B * T * E) / 256, 256>>>(cap, emb, capemb);
    cudaEventRecord(evG, 0);                            // capemb ready (for gatesx on sA)
    row_mean<<<B, 512>>>(feats, meanbf);
    f2bf_copy<<<512, 256>>>(U_a, uabf, (size_t)E * H / 4);
    f2bf_cat<<<(1024 * 1024 / 4) / 256, 256>>>(W_a,    1024, 1024, wqbbf, 1536, 0, 0);
    f2bf_cat<<<(1024 * 512  / 4) / 256, 256>>>(W_beta, 1024, 512,  wqbbf, 1536, 0, 1024);
    f2bf_rows<<<(512  * 4096 / 4) / 256, 256>>>(W_lstm, 0, 4096, 512,  wgbf2, 4096, 0);
    f2bf_rows<<<(1024 * 4096 / 4) / 256, 256>>>(U_lstm, 0, 4096, 1024, wgbf2, 4096, 512);
    f2bf_copy<<<512, 256>>>(W_init_h, wihbf, (size_t)E * H / 4);
    f2bf_copy<<<512, 256>>>(W_init_c, wicbf, (size_t)E * H / 4);
    gemm_hmma<1, true,  true><<<dim3(8, 1), 256, GSMEM>>>(meanbf, wihbf, b_init_h, hslot(0), 128, H, E);
    gemm_hmma<1, false, true><<<dim3(8, 1), 256, GSMEM>>>(meanbf, wicbf, b_init_c, cst, 128, H, E);
    copy_h0<<<(B * H) / 256, 256>>>(hslot(0), ctx2);
    gemm_hmma<1, true, true><<<dim3(8, B * L / 128), 256, GSMEM>>>(featsbf, uabf, b_ua, keys, B * L, H, E);

    // stream A: output-branch weights + gatesx precompute (overlaps keys GEMM)
    f2bf_rows<<<(512 * 4096 / 4) / 256, 256, 0, sA>>>(W_lstm, 512, 4096, 512, wlxbf, 4096, 0);
    f2bf_copy<<<2048, 256, 0, sA>>>(W_out, woutbf, (size_t)H * V / 4);
    cudaStreamWaitEvent(sA, evG, 0);
    gemm_hmma<1, false, true><<<dim3(4096 / 128, (B * T) / 128), 256, GSMEM, sA>>>(
        capemb, wlxbf, b_lstm, gatesx, B * T, 4096, 512);
    cudaEventRecord(evX, sA);
    cudaStreamWaitEvent(0, evX, 0);    // gatesx ready before first lstm_elem (free: keys GEMM outlasts sA)

    // ---- time steps ----
    for (int t = 0; t < T; t++) {
        const __nv_bfloat16* h_in  = hslot(t);          // h(t)
        __nv_bfloat16*       h_out = hslot(t + 1);      // h(t+1) — fresh slot, no reuse

        // attention / LSTM chain (stream 0 = critical path)
        gemm_hmma<4, false, false><<<dim3(12, 1, 4), 256, GSMEM>>>(h_in, wqbbf, nullptr, qbp, 128, 1536, 1024);
        attn_e<<<dim3(7, B), 128>>>(keys, qbp, b_a, V_a, b_va, eb);
        z_ctx<<<B, 512>>>(eb, featsbf, qbp, b_beta, ctx2);
        gemm_hmma<4, false, false><<<dim3(32, 1, 4), 256, GSMEM>>>(ctx2, wgbf2, nullptr, gatesp, 128, 4096, 1536);
        lstm_elem<<<(B * H) / 256, 256>>>(gatesp, gatesx, cst, h_out, ctx2, t);

        // fork: output branch on stream A — BN=128 logits (250 CTAs, 2 CTAs/SM:
        // co-resides with the chain GEMMs instead of excluding them)
        cudaEventRecord(evH[t], 0);
        cudaStreamWaitEvent(sA, evH[t], 0);
        gemm_hmma<1, false, true><<<dim3(V / 128, 1), 256, GSMEM, sA>>>(h_out, woutbf, b_out, logits, 128, V, H);
        softmax_V<<<B, 1024, V * 4, sA>>>(logits, out, t);
    }

    // join output branch back into the main stream
    cudaEventRecord(evO, sA);
    cudaStreamWaitEvent(0, evO, 0);
}